// round 4
// baseline (speedup 1.0000x reference)
#include <cuda_runtime.h>
#include <cstdint>
#include <cstddef>

#define NN    200000
#define EE    200000
#define CIN   512
#define CHID  512
#define COUT  256
#define KHOPS 10
#define CHUNK 12500     // 16 chunks of rows through the MLP

// ---------------- device scratch (static; no allocation) ----------------
__device__ int           g_is64;
__device__ unsigned int  g_degi[NN];
__device__ __align__(16) float g_coef[EE];
__device__ int           g_col[EE];
__device__ __align__(16) float g_tmp[(size_t)CHUNK * CHID];  // per-chunk hidden
__device__ __align__(16) float g_xA[(size_t)NN * COUT];      // ping
__device__ __align__(16) float g_xB[(size_t)NN * COUT];      // pong

// ---------------- edge_index dtype detection ----------------
// int64 little-endian values < 2^31  => all odd 32-bit words are zero.
// genuine int32 data => odd words are random row indices (mostly nonzero).
__global__ void k_detect(const int* __restrict__ buf) {
    __shared__ int nz;
    if (threadIdx.x == 0) nz = 0;
    __syncthreads();
    int local = 0;
    for (int i = threadIdx.x; i < 1024; i += blockDim.x)
        if (buf[2 * i + 1] != 0) local = 1;
    if (local) atomicOr(&nz, 1);
    __syncthreads();
    if (threadIdx.x == 0) g_is64 = (nz == 0) ? 1 : 0;
}

__device__ __forceinline__ int edge_row(const int* buf, int e) {
    int v = g_is64 ? buf[2 * e] : buf[e];
    unsigned u = (unsigned)v;
    return (u < NN) ? (int)u : 0;     // defensive clamp
}
__device__ __forceinline__ int edge_col(const int* buf, int e) {
    int v = g_is64 ? buf[2 * (EE + e)] : buf[EE + e];
    unsigned u = (unsigned)v;
    return (u < NN) ? (int)u : 0;
}

// ---------------- graph prep ----------------
__global__ void k_zero_deg() {
    int i = blockIdx.x * blockDim.x + threadIdx.x;
    if (i < NN) g_degi[i] = 0u;
}

__global__ void k_count(const int* __restrict__ ei) {
    int e = blockIdx.x * blockDim.x + threadIdx.x;
    if (e < EE) atomicAdd(&g_degi[edge_row(ei, e)], 1u);
}

__global__ void k_coef(const int* __restrict__ ei) {
    int e = blockIdx.x * blockDim.x + threadIdx.x;
    if (e >= EE) return;
    int r = edge_row(ei, e);
    int c = edge_col(ei, e);
    float dr = (float)g_degi[r], dc = (float)g_degi[c];
    float ir = dr > 0.f ? rsqrtf(dr) : 0.f;
    float ic = dc > 0.f ? rsqrtf(dc) : 0.f;
    g_coef[e] = ir * ic;
    g_col[e]  = c;
}

// ---------------- fp32 tiled GEMM ----------------
// MODE 0: C = relu(A@B + bias) -> g_tmp          (A = x chunk, pre-offset)
// MODE 1: C = A@B + bias -> g_xA+row0*COUT, and out = gamma[0]*C  (A = g_tmp)
#define BM  128
#define BN  64
#define BKK 16

template<int MODE>
__global__ __launch_bounds__(256)
void k_gemm(const float* __restrict__ A_in, const float* __restrict__ B,
            const float* __restrict__ bias, const float* __restrict__ gamma,
            float* __restrict__ out, int M, int Ncols, int Kdim, int row0)
{
    __shared__ float As[BKK][BM];
    __shared__ float Bs[BKK][BN];

    const float* A = (MODE == 0) ? A_in : g_tmp;
    float*       C = (MODE == 0) ? g_tmp : (g_xA + (size_t)row0 * COUT);

    const int tid = threadIdx.x;
    const int tx  = tid & 15;    // 0..15  (BN/4 = 16 columns of 4)
    const int ty  = tid >> 4;    // 0..15  (BM/8 = 16 rows of 8)
    const int m0  = blockIdx.y * BM;
    const int n0  = blockIdx.x * BN;

    float acc[8][4];
#pragma unroll
    for (int i = 0; i < 8; ++i)
#pragma unroll
        for (int j = 0; j < 4; ++j) acc[i][j] = 0.f;

    const int aRow = tid >> 2;          // 0..63
    const int aCol = (tid & 3) << 2;    // 0,4,8,12
    const int bRow = tid >> 4;          // 0..15
    const int bCol = (tid & 15) << 2;   // 0..60

    for (int k0 = 0; k0 < Kdim; k0 += BKK) {
#pragma unroll
        for (int r = 0; r < 2; ++r) {
            int m  = m0 + aRow + r * 64;
            int mm = (m < M) ? m : (M - 1);       // clamp; stores guarded later
            float4 v = *(const float4*)(A + (size_t)mm * Kdim + k0 + aCol);
            As[aCol + 0][aRow + r * 64] = v.x;
            As[aCol + 1][aRow + r * 64] = v.y;
            As[aCol + 2][aRow + r * 64] = v.z;
            As[aCol + 3][aRow + r * 64] = v.w;
        }
        {
            float4 v = *(const float4*)(B + (size_t)(k0 + bRow) * Ncols + n0 + bCol);
            *(float4*)&Bs[bRow][bCol] = v;
        }
        __syncthreads();

#pragma unroll
        for (int kk = 0; kk < BKK; ++kk) {
            float4 a0 = *(const float4*)&As[kk][ty * 8];
            float4 a1 = *(const float4*)&As[kk][ty * 8 + 4];
            float4 b  = *(const float4*)&Bs[kk][tx * 4];
            float av[8] = {a0.x, a0.y, a0.z, a0.w, a1.x, a1.y, a1.z, a1.w};
            float bv[4] = {b.x, b.y, b.z, b.w};
#pragma unroll
            for (int i = 0; i < 8; ++i)
#pragma unroll
                for (int j = 0; j < 4; ++j)
                    acc[i][j] = fmaf(av[i], bv[j], acc[i][j]);
        }
        __syncthreads();
    }

    float4 bb = *(const float4*)(bias + n0 + tx * 4);
    float g0 = 0.f;
    if (MODE == 1) g0 = gamma[0];

#pragma unroll
    for (int i = 0; i < 8; ++i) {
        int m = m0 + ty * 8 + i;
        if (m < M) {
            float4 v;
            v.x = acc[i][0] + bb.x;
            v.y = acc[i][1] + bb.y;
            v.z = acc[i][2] + bb.z;
            v.w = acc[i][3] + bb.w;
            size_t off = (size_t)m * Ncols + n0 + tx * 4;
            if (MODE == 0) {
                v.x = fmaxf(v.x, 0.f);
                v.y = fmaxf(v.y, 0.f);
                v.z = fmaxf(v.z, 0.f);
                v.w = fmaxf(v.w, 0.f);
                *(float4*)(C + off) = v;
            } else {
                *(float4*)(C + off) = v;
                float4 o;
                o.x = g0 * v.x;
                o.y = g0 * v.y;
                o.z = g0 * v.z;
                o.w = g0 * v.w;
                *(float4*)(out + off) = o;   // out pre-offset by row0*COUT
            }
        }
    }
}

// ---------------- propagation hop ----------------
// x_new[e] = relu(coef[e] * x_old[col[e]]);  out[e] += gamma[k] * x_new[e]
__global__ __launch_bounds__(256)
void k_hop(int flip, const float* __restrict__ gamma, int k, int write_x,
           float* __restrict__ out)
{
    int t = blockIdx.x * blockDim.x + threadIdx.x;
    if (t >= EE * (COUT / 4)) return;
    int e = t >> 6;            // 64 float4 per row
    int c = (t & 63) << 2;

    const float* xold = flip ? g_xB : g_xA;
    float*       xnew = flip ? g_xA : g_xB;

    int   src = g_col[e];      // broadcast within 2 warps per row
    float cf  = g_coef[e];
    float g   = gamma[k];

    float4 v = *(const float4*)(xold + (size_t)src * COUT + c);
    float4 r;
    r.x = fmaxf(cf * v.x, 0.f);
    r.y = fmaxf(cf * v.y, 0.f);
    r.z = fmaxf(cf * v.z, 0.f);
    r.w = fmaxf(cf * v.w, 0.f);

    size_t off = (size_t)e * COUT + c;
    if (write_x) *(float4*)(xnew + off) = r;

    float4 o = *(const float4*)(out + off);
    o.x = fmaf(g, r.x, o.x);
    o.y = fmaf(g, r.y, o.y);
    o.z = fmaf(g, r.z, o.z);
    o.w = fmaf(g, r.w, o.w);
    *(float4*)(out + off) = o;
}

// ---------------- launch ----------------
extern "C" void kernel_launch(void* const* d_in, const int* in_sizes, int n_in,
                              void* d_out, int out_size)
{
    // Identify inputs by element count (robust to metadata ordering).
    const float* x     = nullptr;
    const int*   ei    = nullptr;   // int32 or int64 raw words; detected on device
    const float* W1    = nullptr;
    const float* b1    = nullptr;
    const float* W2    = nullptr;
    const float* b2    = nullptr;
    const float* gamma = nullptr;
    for (int i = 0; i < n_in; ++i) {
        switch (in_sizes[i]) {
            case 102400000: x     = (const float*)d_in[i]; break; // N*512
            case 400000:    ei    = (const int*)d_in[i];   break; // 2*E
            case 262144:    W1    = (const float*)d_in[i]; break; // 512*512
            case 512:       b1    = (const float*)d_in[i]; break;
            case 131072:    W2    = (const float*)d_in[i]; break; // 512*256
            case 256:       b2    = (const float*)d_in[i]; break;
            case 11:        gamma = (const float*)d_in[i]; break;
        }
    }
    float* out = (float*)d_out;

    k_detect<<<1, 256>>>(ei);
    k_zero_deg<<<(NN + 255) / 256, 256>>>();
    k_count<<<(EE + 255) / 256, 256>>>(ei);
    k_coef<<<(EE + 255) / 256, 256>>>(ei);

    // MLP in row chunks: GEMM1 -> g_tmp, GEMM2 -> g_xA (+ out = gamma0 * h)
    dim3 g1(CHID / BN, (CHUNK + BM - 1) / BM);
    dim3 g2(COUT / BN, (CHUNK + BM - 1) / BM);
    for (int row0 = 0; row0 < NN; row0 += CHUNK) {
        k_gemm<0><<<g1, 256>>>(x + (size_t)row0 * CIN, W1, b1, gamma,
                               out, CHUNK, CHID, CIN, row0);
        k_gemm<1><<<g2, 256>>>(nullptr, W2, b2, gamma,
                               out + (size_t)row0 * COUT, CHUNK, COUT, CHID, row0);
    }

    const int total  = EE * (COUT / 4);
    const int blocks = (total + 255) / 256;
    for (int k = 1; k <= KHOPS; ++k) {
        k_hop<<<blocks, 256>>>((k - 1) & 1, gamma, k, (k < KHOPS) ? 1 : 0, out);
    }
}

// round 7
// speedup vs baseline: 1.6112x; 1.6112x over previous
#include <cuda_runtime.h>
#include <cuda_bf16.h>
#include <cstdint>
#include <cstddef>

#define NN    200000
#define EE    200000
#define CIN   512
#define CHID  512
#define COUT  256
#define KHOPS 10
#define CHUNK 50000     // 4 chunks of rows through the MLP

// ---------------- device scratch (static; no allocation) ----------------
__device__ int           g_is64;
__device__ unsigned int  g_degi[NN];
__device__ __align__(16) float g_coef[EE];
__device__ int           g_col[EE];
__device__ __align__(16) float g_tmp[(size_t)CHUNK * CHID];  // per-chunk hidden
__device__ __align__(16) float g_xA[(size_t)NN * COUT];      // ping
__device__ __align__(16) float g_xB[(size_t)NN * COUT];      // pong
// transposed + bf16-split weights: Wt[n][k] = W[k][n]  (k-major = mma "col" B)
__device__ __align__(16) __nv_bfloat16 g_W1h[(size_t)CHID * CIN];
__device__ __align__(16) __nv_bfloat16 g_W1l[(size_t)CHID * CIN];
__device__ __align__(16) __nv_bfloat16 g_W2h[(size_t)COUT * CHID];
__device__ __align__(16) __nv_bfloat16 g_W2l[(size_t)COUT * CHID];

// ---------------- edge_index dtype detection ----------------
__global__ void k_detect(const int* __restrict__ buf) {
    __shared__ int nz;
    if (threadIdx.x == 0) nz = 0;
    __syncthreads();
    int local = 0;
    for (int i = threadIdx.x; i < 1024; i += blockDim.x)
        if (buf[2 * i + 1] != 0) local = 1;
    if (local) atomicOr(&nz, 1);
    __syncthreads();
    if (threadIdx.x == 0) g_is64 = (nz == 0) ? 1 : 0;
}

__device__ __forceinline__ int edge_row(const int* buf, int e) {
    int v = g_is64 ? buf[2 * e] : buf[e];
    unsigned u = (unsigned)v;
    return (u < NN) ? (int)u : 0;
}
__device__ __forceinline__ int edge_col(const int* buf, int e) {
    int v = g_is64 ? buf[2 * (EE + e)] : buf[EE + e];
    unsigned u = (unsigned)v;
    return (u < NN) ? (int)u : 0;
}

// ---------------- graph prep ----------------
__global__ void k_zero_deg() {
    int i = blockIdx.x * blockDim.x + threadIdx.x;
    if (i < NN) g_degi[i] = 0u;
}
__global__ void k_count(const int* __restrict__ ei) {
    int e = blockIdx.x * blockDim.x + threadIdx.x;
    if (e < EE) atomicAdd(&g_degi[edge_row(ei, e)], 1u);
}
__global__ void k_coef(const int* __restrict__ ei) {
    int e = blockIdx.x * blockDim.x + threadIdx.x;
    if (e >= EE) return;
    int r = edge_row(ei, e);
    int c = edge_col(ei, e);
    float dr = (float)g_degi[r], dc = (float)g_degi[c];
    float ir = dr > 0.f ? rsqrtf(dr) : 0.f;
    float ic = dc > 0.f ? rsqrtf(dc) : 0.f;
    g_coef[e] = ir * ic;
    g_col[e]  = c;
}

// ---------------- weight transpose + bf16 split ----------------
__global__ void k_prep_w(const float* __restrict__ W, __nv_bfloat16* __restrict__ Th,
                         __nv_bfloat16* __restrict__ Tl, int Kdim, int Ncols) {
    int i = blockIdx.x * blockDim.x + threadIdx.x;
    if (i >= Kdim * Ncols) return;
    int n = i / Kdim, k = i % Kdim;
    float v = W[(size_t)k * Ncols + n];
    __nv_bfloat16 h = __float2bfloat16_rn(v);
    Th[i] = h;
    Tl[i] = __float2bfloat16_rn(v - __bfloat162float(h));
}

// ---------------- warp-MMA bf16-split GEMM ----------------
// C[M,N] = A[M,K] @ Bt[N,K]^T + bias; split bf16, 3 cross terms, fp32 acc.
// MODE 0: relu -> Cout.   MODE 1: Cout = v, Oout = gamma[0]*v.
// CTA tile 128x128, BK=32, 8 warps in 2(M) x 4(N), warp tile 64x32.
#define RSTR 20   // smem row stride in b32 units (16 data + 4 pad)

__device__ __forceinline__ void mma_bf16(float& d0, float& d1, float& d2, float& d3,
                                         uint32_t a0, uint32_t a1, uint32_t a2, uint32_t a3,
                                         uint32_t b0, uint32_t b1) {
    asm volatile(
        "mma.sync.aligned.m16n8k16.row.col.f32.bf16.bf16.f32 "
        "{%0,%1,%2,%3}, {%4,%5,%6,%7}, {%8,%9}, {%0,%1,%2,%3};"
        : "+f"(d0), "+f"(d1), "+f"(d2), "+f"(d3)
        : "r"(a0), "r"(a1), "r"(a2), "r"(a3), "r"(b0), "r"(b1));
}

template<int MODE>
__global__ void __launch_bounds__(256, 2)
k_gemm_mma(const float* __restrict__ A,
           const __nv_bfloat16* __restrict__ Bth,
           const __nv_bfloat16* __restrict__ Btl,
           const float* __restrict__ bias,
           const float* __restrict__ gamma,
           float* __restrict__ Cout,
           float* __restrict__ Oout,
           int Mrows, int Ncols, int Kdim)
{
    __shared__ uint32_t sAh[128 * RSTR];
    __shared__ uint32_t sAl[128 * RSTR];
    __shared__ uint32_t sBh[128 * RSTR];
    __shared__ uint32_t sBl[128 * RSTR];

    const int tid  = threadIdx.x;
    const int wid  = tid >> 5;
    const int lane = tid & 31;
    const int wm   = wid >> 2;          // 0..1
    const int wn   = wid & 3;           // 0..3
    const int m0   = blockIdx.y * 128;
    const int n0   = blockIdx.x * 128;

    float acc[4][4][4];
#pragma unroll
    for (int i = 0; i < 4; ++i)
#pragma unroll
        for (int j = 0; j < 4; ++j)
#pragma unroll
            for (int r = 0; r < 4; ++r) acc[i][j][r] = 0.f;

    const int ldRow  = tid >> 1;        // 0..127
    const int ldHalf = tid & 1;         // k sub-range of 16

    for (int k0 = 0; k0 < Kdim; k0 += 32) {
        // ---- stage A: load fp32, split to bf16 hi/lo (16 bf16 / thread) ----
        {
            int m = m0 + ldRow;
            if (m >= Mrows) m = Mrows - 1;
            const float4* src = (const float4*)(A + (size_t)m * Kdim + k0 + ldHalf * 16);
            uint32_t h[8], l[8];
#pragma unroll
            for (int q = 0; q < 4; ++q) {
                float4 v = src[q];
                float f[4] = {v.x, v.y, v.z, v.w};
#pragma unroll
                for (int p = 0; p < 2; ++p) {
                    __nv_bfloat16 h0 = __float2bfloat16_rn(f[2 * p]);
                    __nv_bfloat16 h1 = __float2bfloat16_rn(f[2 * p + 1]);
                    __nv_bfloat16 l0 = __float2bfloat16_rn(f[2 * p]     - __bfloat162float(h0));
                    __nv_bfloat16 l1 = __float2bfloat16_rn(f[2 * p + 1] - __bfloat162float(h1));
                    h[q * 2 + p] = ((uint32_t)__bfloat16_as_ushort(h1) << 16) | __bfloat16_as_ushort(h0);
                    l[q * 2 + p] = ((uint32_t)__bfloat16_as_ushort(l1) << 16) | __bfloat16_as_ushort(l0);
                }
            }
            uint32_t* dh = &sAh[ldRow * RSTR + ldHalf * 8];
            uint32_t* dl = &sAl[ldRow * RSTR + ldHalf * 8];
            *(uint4*)(dh + 0) = make_uint4(h[0], h[1], h[2], h[3]);
            *(uint4*)(dh + 4) = make_uint4(h[4], h[5], h[6], h[7]);
            *(uint4*)(dl + 0) = make_uint4(l[0], l[1], l[2], l[3]);
            *(uint4*)(dl + 4) = make_uint4(l[4], l[5], l[6], l[7]);
        }
        // ---- stage B: pre-split bf16 (16 bf16 / thread = 2 uint4 each) ----
        {
            size_t goff = (size_t)(n0 + ldRow) * Kdim + k0 + ldHalf * 16;
            uint4 vh0 = *(const uint4*)(Bth + goff);
            uint4 vh1 = *(const uint4*)(Bth + goff + 8);
            uint4 vl0 = *(const uint4*)(Btl + goff);
            uint4 vl1 = *(const uint4*)(Btl + goff + 8);
            uint32_t* dbh = &sBh[ldRow * RSTR + ldHalf * 8];
            uint32_t* dbl = &sBl[ldRow * RSTR + ldHalf * 8];
            *(uint4*)(dbh + 0) = vh0;
            *(uint4*)(dbh + 4) = vh1;
            *(uint4*)(dbl + 0) = vl0;
            *(uint4*)(dbl + 4) = vl1;
        }
        __syncthreads();

        // ---- compute: 2 k16 sub-steps ----
#pragma unroll
        for (int ks = 0; ks < 2; ++ks) {
            const int kp = ks * 8 + (lane & 3);
            uint32_t ah[4][4], bh[4][2], bl[4][2], al[4][4];
            // A-hi fragments
#pragma unroll
            for (int i = 0; i < 4; ++i) {
                int r = (wm * 64 + i * 16 + (lane >> 2)) * RSTR + kp;
                ah[i][0] = sAh[r];
                ah[i][1] = sAh[r + 8 * RSTR];
                ah[i][2] = sAh[r + 4];
                ah[i][3] = sAh[r + 8 * RSTR + 4];
            }
            // B-hi fragments
#pragma unroll
            for (int j = 0; j < 4; ++j) {
                int r = (wn * 32 + j * 8 + (lane >> 2)) * RSTR + kp;
                bh[j][0] = sBh[r];
                bh[j][1] = sBh[r + 4];
            }
#pragma unroll
            for (int i = 0; i < 4; ++i)
#pragma unroll
                for (int j = 0; j < 4; ++j)
                    mma_bf16(acc[i][j][0], acc[i][j][1], acc[i][j][2], acc[i][j][3],
                             ah[i][0], ah[i][1], ah[i][2], ah[i][3], bh[j][0], bh[j][1]);
            // B-lo fragments : Ah * Bl
#pragma unroll
            for (int j = 0; j < 4; ++j) {
                int r = (wn * 32 + j * 8 + (lane >> 2)) * RSTR + kp;
                bl[j][0] = sBl[r];
                bl[j][1] = sBl[r + 4];
            }
#pragma unroll
            for (int i = 0; i < 4; ++i)
#pragma unroll
                for (int j = 0; j < 4; ++j)
                    mma_bf16(acc[i][j][0], acc[i][j][1], acc[i][j][2], acc[i][j][3],
                             ah[i][0], ah[i][1], ah[i][2], ah[i][3], bl[j][0], bl[j][1]);
            // A-lo fragments : Al * Bh
#pragma unroll
            for (int i = 0; i < 4; ++i) {
                int r = (wm * 64 + i * 16 + (lane >> 2)) * RSTR + kp;
                al[i][0] = sAl[r];
                al[i][1] = sAl[r + 8 * RSTR];
                al[i][2] = sAl[r + 4];
                al[i][3] = sAl[r + 8 * RSTR + 4];
            }
#pragma unroll
            for (int i = 0; i < 4; ++i)
#pragma unroll
                for (int j = 0; j < 4; ++j)
                    mma_bf16(acc[i][j][0], acc[i][j][1], acc[i][j][2], acc[i][j][3],
                             al[i][0], al[i][1], al[i][2], al[i][3], bh[j][0], bh[j][1]);
        }
        __syncthreads();
    }

    // ---- epilogue ----
    float g0 = 0.f;
    if (MODE == 1) g0 = gamma[0];

#pragma unroll
    for (int i = 0; i < 4; ++i) {
#pragma unroll
        for (int j = 0; j < 4; ++j) {
            int cn = n0 + wn * 32 + j * 8 + 2 * (lane & 3);
            float2 bb = *(const float2*)(bias + cn);
            int rm = m0 + wm * 64 + i * 16 + (lane >> 2);
#pragma unroll
            for (int h = 0; h < 2; ++h) {
                int r = rm + h * 8;
                if (r < Mrows) {
                    float2 v;
                    v.x = acc[i][j][2 * h + 0] + bb.x;
                    v.y = acc[i][j][2 * h + 1] + bb.y;
                    size_t off = (size_t)r * Ncols + cn;
                    if (MODE == 0) {
                        v.x = fmaxf(v.x, 0.f);
                        v.y = fmaxf(v.y, 0.f);
                        *(float2*)(Cout + off) = v;
                    } else {
                        *(float2*)(Cout + off) = v;
                        float2 o;
                        o.x = g0 * v.x;
                        o.y = g0 * v.y;
                        *(float2*)(Oout + off) = o;
                    }
                }
            }
        }
    }
}

// ---------------- propagation hop ----------------
__global__ __launch_bounds__(256)
void k_hop(int flip, const float* __restrict__ gamma, int k, int write_x,
           float* __restrict__ out)
{
    int t = blockIdx.x * blockDim.x + threadIdx.x;
    if (t >= EE * (COUT / 4)) return;
    int e = t >> 6;
    int c = (t & 63) << 2;

    const float* xold = flip ? g_xB : g_xA;
    float*       xnew = flip ? g_xA : g_xB;

    int   src = g_col[e];
    float cf  = g_coef[e];
    float g   = gamma[k];

    float4 v = *(const float4*)(xold + (size_t)src * COUT + c);
    float4 r;
    r.x = fmaxf(cf * v.x, 0.f);
    r.y = fmaxf(cf * v.y, 0.f);
    r.z = fmaxf(cf * v.z, 0.f);
    r.w = fmaxf(cf * v.w, 0.f);

    size_t off = (size_t)e * COUT + c;
    if (write_x) *(float4*)(xnew + off) = r;

    float4 o = *(const float4*)(out + off);
    o.x = fmaf(g, r.x, o.x);
    o.y = fmaf(g, r.y, o.y);
    o.z = fmaf(g, r.z, o.z);
    o.w = fmaf(g, r.w, o.w);
    *(float4*)(out + off) = o;
}

// ---------------- launch ----------------
extern "C" void kernel_launch(void* const* d_in, const int* in_sizes, int n_in,
                              void* d_out, int out_size)
{
    const float* x     = nullptr;
    const int*   ei    = nullptr;
    const float* W1    = nullptr;
    const float* b1    = nullptr;
    const float* W2    = nullptr;
    const float* b2    = nullptr;
    const float* gamma = nullptr;
    for (int i = 0; i < n_in; ++i) {
        switch (in_sizes[i]) {
            case 102400000: x     = (const float*)d_in[i]; break;
            case 400000:    ei    = (const int*)d_in[i];   break;
            case 262144:    W1    = (const float*)d_in[i]; break;
            case 512:       b1    = (const float*)d_in[i]; break;
            case 131072:    W2    = (const float*)d_in[i]; break;
            case 256:       b2    = (const float*)d_in[i]; break;
            case 11:        gamma = (const float*)d_in[i]; break;
        }
    }
    float* out = (float*)d_out;

    k_detect<<<1, 256>>>(ei);
    k_zero_deg<<<(NN + 255) / 256, 256>>>();
    k_count<<<(EE + 255) / 256, 256>>>(ei);
    k_coef<<<(EE + 255) / 256, 256>>>(ei);

    __nv_bfloat16 *w1h, *w1l, *w2h, *w2l;
    cudaGetSymbolAddress((void**)&w1h, g_W1h);
    cudaGetSymbolAddress((void**)&w1l, g_W1l);
    cudaGetSymbolAddress((void**)&w2h, g_W2h);
    cudaGetSymbolAddress((void**)&w2l, g_W2l);
    k_prep_w<<<(CIN * CHID + 255) / 256, 256>>>(W1, w1h, w1l, CIN, CHID);
    k_prep_w<<<(CHID * COUT + 255) / 256, 256>>>(W2, w2h, w2l, CHID, COUT);

    float *tmp, *xA;
    cudaGetSymbolAddress((void**)&tmp, g_tmp);
    cudaGetSymbolAddress((void**)&xA,  g_xA);

    const int mt = (CHUNK + 127) / 128;
    dim3 g1(CHID / 128, mt);
    dim3 g2(COUT / 128, mt);
    for (int row0 = 0; row0 < NN; row0 += CHUNK) {
        k_gemm_mma<0><<<g1, 256>>>(
            x + (size_t)row0 * CIN, w1h, w1l, b1, gamma,
            tmp, nullptr, CHUNK, CHID, CIN);
        k_gemm_mma<1><<<g2, 256>>>(
            tmp, w2h, w2l, b2, gamma,
            xA + (size_t)row0 * COUT, out + (size_t)row0 * COUT, CHUNK, COUT, CHID);
    }

    const int total  = EE * (COUT / 4);
    const int blocks = (total + 255) / 256;
    for (int k = 1; k <= KHOPS; ++k) {
        k_hop<<<blocks, 256>>>((k - 1) & 1, gamma, k, (k < KHOPS) ? 1 : 0, out);
    }
}

// round 8
// speedup vs baseline: 3.0388x; 1.8860x over previous
#include <cuda_runtime.h>
#include <cuda_bf16.h>
#include <cstdint>
#include <cstddef>

#define NN    200000
#define EE    200000
#define CIN   512
#define CHID  512
#define COUT  256
#define KHOPS 10
#define CHUNK 50000     // 4 chunks of rows through the MLP

// ---------------- device scratch (static; no allocation) ----------------
__device__ int           g_is64;
__device__ unsigned int  g_degi[NN];
__device__ __align__(16) float g_coef[EE];
__device__ int           g_col[EE];
__device__ int           g_idx[(size_t)KHOPS * EE];   // col^k chains
__device__ __align__(16) float g_P[(size_t)KHOPS * EE]; // cumulative coef products
__device__ __align__(16) float g_h[(size_t)NN * COUT];  // MLP output (fp32)
// per-chunk split activations
__device__ __align__(16) __nv_bfloat16 g_xh[(size_t)CHUNK * CIN];
__device__ __align__(16) __nv_bfloat16 g_xl[(size_t)CHUNK * CIN];
__device__ __align__(16) __nv_bfloat16 g_t1h[(size_t)CHUNK * CHID];
__device__ __align__(16) __nv_bfloat16 g_t1l[(size_t)CHUNK * CHID];
// transposed + bf16-split weights: Wt[n][k] = W[k][n]
__device__ __align__(16) __nv_bfloat16 g_W1h[(size_t)CHID * CIN];
__device__ __align__(16) __nv_bfloat16 g_W1l[(size_t)CHID * CIN];
__device__ __align__(16) __nv_bfloat16 g_W2h[(size_t)COUT * CHID];
__device__ __align__(16) __nv_bfloat16 g_W2l[(size_t)COUT * CHID];

// ---------------- edge_index dtype detection ----------------
__global__ void k_detect(const int* __restrict__ buf) {
    __shared__ int nz;
    if (threadIdx.x == 0) nz = 0;
    __syncthreads();
    int local = 0;
    for (int i = threadIdx.x; i < 1024; i += blockDim.x)
        if (buf[2 * i + 1] != 0) local = 1;
    if (local) atomicOr(&nz, 1);
    __syncthreads();
    if (threadIdx.x == 0) g_is64 = (nz == 0) ? 1 : 0;
}
__device__ __forceinline__ int edge_row(const int* buf, int e) {
    int v = g_is64 ? buf[2 * e] : buf[e];
    unsigned u = (unsigned)v;
    return (u < NN) ? (int)u : 0;
}
__device__ __forceinline__ int edge_col(const int* buf, int e) {
    int v = g_is64 ? buf[2 * (EE + e)] : buf[EE + e];
    unsigned u = (unsigned)v;
    return (u < NN) ? (int)u : 0;
}

// ---------------- graph prep ----------------
__global__ void k_zero_deg() {
    int i = blockIdx.x * blockDim.x + threadIdx.x;
    if (i < NN) g_degi[i] = 0u;
}
__global__ void k_count(const int* __restrict__ ei) {
    int e = blockIdx.x * blockDim.x + threadIdx.x;
    if (e < EE) atomicAdd(&g_degi[edge_row(ei, e)], 1u);
}
__global__ void k_coef(const int* __restrict__ ei) {
    int e = blockIdx.x * blockDim.x + threadIdx.x;
    if (e >= EE) return;
    int r = edge_row(ei, e);
    int c = edge_col(ei, e);
    float dr = (float)g_degi[r], dc = (float)g_degi[c];
    float ir = dr > 0.f ? rsqrtf(dr) : 0.f;
    float ic = dc > 0.f ? rsqrtf(dc) : 0.f;
    g_coef[e] = ir * ic;
    g_col[e]  = c;
}

// ---------------- hop-chain precompute ----------------
// idx_k[e] = col^k[e], P_k[e] = prod_{j<k} coef[col^j[e]]
__global__ void k_chain_init() {
    int e = blockIdx.x * blockDim.x + threadIdx.x;
    if (e >= EE) return;
    g_idx[e] = g_col[e];
    g_P[e]   = g_coef[e];
}
__global__ void k_chain_step(int k) {   // produces level k+1 (store at [k])
    int e = blockIdx.x * blockDim.x + threadIdx.x;
    if (e >= EE) return;
    int p = g_idx[(size_t)(k - 1) * EE + e];
    g_idx[(size_t)k * EE + e] = g_col[p];
    g_P[(size_t)k * EE + e]   = g_P[(size_t)(k - 1) * EE + e] * g_coef[p];
}

// ---------------- weight transpose + bf16 split ----------------
__global__ void k_prep_w(const float* __restrict__ W, __nv_bfloat16* __restrict__ Th,
                         __nv_bfloat16* __restrict__ Tl, int Kdim, int Ncols) {
    int i = blockIdx.x * blockDim.x + threadIdx.x;
    if (i >= Kdim * Ncols) return;
    int n = i / Kdim, k = i % Kdim;
    float v = W[(size_t)k * Ncols + n];
    __nv_bfloat16 h = __float2bfloat16_rn(v);
    Th[i] = h;
    Tl[i] = __float2bfloat16_rn(v - __bfloat162float(h));
}

// ---------------- fp32 -> bf16 hi/lo split (x chunk) ----------------
__global__ void k_split(const float* __restrict__ src,
                        __nv_bfloat16* __restrict__ Th,
                        __nv_bfloat16* __restrict__ Tl, int n4) {
    int i = blockIdx.x * blockDim.x + threadIdx.x;
    if (i >= n4) return;
    float4 v = ((const float4*)src)[i];
    float f[4] = {v.x, v.y, v.z, v.w};
    uint32_t h[2], l[2];
#pragma unroll
    for (int p = 0; p < 2; ++p) {
        __nv_bfloat16 h0 = __float2bfloat16_rn(f[2 * p]);
        __nv_bfloat16 h1 = __float2bfloat16_rn(f[2 * p + 1]);
        __nv_bfloat16 l0 = __float2bfloat16_rn(f[2 * p]     - __bfloat162float(h0));
        __nv_bfloat16 l1 = __float2bfloat16_rn(f[2 * p + 1] - __bfloat162float(h1));
        h[p] = ((uint32_t)__bfloat16_as_ushort(h1) << 16) | __bfloat16_as_ushort(h0);
        l[p] = ((uint32_t)__bfloat16_as_ushort(l1) << 16) | __bfloat16_as_ushort(l0);
    }
    ((uint2*)Th)[i] = make_uint2(h[0], h[1]);
    ((uint2*)Tl)[i] = make_uint2(l[0], l[1]);
}

// ---------------- warp-MMA bf16-split GEMM, cp.async double-buffered ----------------
// CTA tile 128x128, BK=32, 8 warps 2(M)x4(N), warp tile 64x32.
// Stage layout (bytes, per stage): Ah[0,10240) Al[10240,20480) Bh[20480,30720) Bl[30720,40960)
// row stride 80B (16 data b32 + 4 pad)
#define RSTR     20
#define ARR_B    10240
#define STG_B    40960

__device__ __forceinline__ void cpa16(uint32_t dst, const void* src) {
    asm volatile("cp.async.cg.shared.global [%0], [%1], 16;" :: "r"(dst), "l"(src));
}
__device__ __forceinline__ void cpa_commit() {
    asm volatile("cp.async.commit_group;");
}
template<int N>
__device__ __forceinline__ void cpa_wait() {
    asm volatile("cp.async.wait_group %0;" :: "n"(N));
}

__device__ __forceinline__ void mma_bf16(float& d0, float& d1, float& d2, float& d3,
                                         uint32_t a0, uint32_t a1, uint32_t a2, uint32_t a3,
                                         uint32_t b0, uint32_t b1) {
    asm volatile(
        "mma.sync.aligned.m16n8k16.row.col.f32.bf16.bf16.f32 "
        "{%0,%1,%2,%3}, {%4,%5,%6,%7}, {%8,%9}, {%0,%1,%2,%3};"
        : "+f"(d0), "+f"(d1), "+f"(d2), "+f"(d3)
        : "r"(a0), "r"(a1), "r"(a2), "r"(a3), "r"(b0), "r"(b1));
}

__device__ __forceinline__ void stage_load(uint32_t smb, int s,
        const __nv_bfloat16* Ah, const __nv_bfloat16* Al,
        const __nv_bfloat16* Bh, const __nv_bfloat16* Bl,
        int m0, int n0, int k0, int Mrows, int Kdim, int tid)
{
    uint32_t base = smb + s * STG_B;
#pragma unroll
    for (int uu = 0; uu < 2; ++uu) {
        int u   = tid + uu * 256;
        int row = u >> 2, seg = u & 3;
        int m = m0 + row;
        if (m >= Mrows) m = Mrows - 1;
        size_t ao = (size_t)m * Kdim + k0 + seg * 8;
        size_t bo = (size_t)(n0 + row) * Kdim + k0 + seg * 8;
        uint32_t d = base + row * 80 + seg * 16;
        cpa16(d,             Ah + ao);
        cpa16(d + ARR_B,     Al + ao);
        cpa16(d + 2 * ARR_B, Bh + bo);
        cpa16(d + 3 * ARR_B, Bl + bo);
    }
}

__device__ __forceinline__ void compute_stage(const uint32_t* sAh, const uint32_t* sAl,
        const uint32_t* sBh, const uint32_t* sBl,
        int wm, int wn, int lane, float acc[4][4][4])
{
#pragma unroll
    for (int ks = 0; ks < 2; ++ks) {
        const int kp = ks * 8 + (lane & 3);
        uint32_t ah[4][4], bh[4][2], bl[4][2], al[4][4];
#pragma unroll
        for (int i = 0; i < 4; ++i) {
            int r = (wm * 64 + i * 16 + (lane >> 2)) * RSTR + kp;
            ah[i][0] = sAh[r];
            ah[i][1] = sAh[r + 8 * RSTR];
            ah[i][2] = sAh[r + 4];
            ah[i][3] = sAh[r + 8 * RSTR + 4];
        }
#pragma unroll
        for (int j = 0; j < 4; ++j) {
            int r = (wn * 32 + j * 8 + (lane >> 2)) * RSTR + kp;
            bh[j][0] = sBh[r];
            bh[j][1] = sBh[r + 4];
        }
#pragma unroll
        for (int i = 0; i < 4; ++i)
#pragma unroll
            for (int j = 0; j < 4; ++j)
                mma_bf16(acc[i][j][0], acc[i][j][1], acc[i][j][2], acc[i][j][3],
                         ah[i][0], ah[i][1], ah[i][2], ah[i][3], bh[j][0], bh[j][1]);
#pragma unroll
        for (int j = 0; j < 4; ++j) {
            int r = (wn * 32 + j * 8 + (lane >> 2)) * RSTR + kp;
            bl[j][0] = sBl[r];
            bl[j][1] = sBl[r + 4];
        }
#pragma unroll
        for (int i = 0; i < 4; ++i)
#pragma unroll
            for (int j = 0; j < 4; ++j)
                mma_bf16(acc[i][j][0], acc[i][j][1], acc[i][j][2], acc[i][j][3],
                         ah[i][0], ah[i][1], ah[i][2], ah[i][3], bl[j][0], bl[j][1]);
#pragma unroll
        for (int i = 0; i < 4; ++i) {
            int r = (wm * 64 + i * 16 + (lane >> 2)) * RSTR + kp;
            al[i][0] = sAl[r];
            al[i][1] = sAl[r + 8 * RSTR];
            al[i][2] = sAl[r + 4];
            al[i][3] = sAl[r + 8 * RSTR + 4];
        }
#pragma unroll
        for (int i = 0; i < 4; ++i)
#pragma unroll
            for (int j = 0; j < 4; ++j)
                mma_bf16(acc[i][j][0], acc[i][j][1], acc[i][j][2], acc[i][j][3],
                         al[i][0], al[i][1], al[i][2], al[i][3], bh[j][0], bh[j][1]);
    }
}

// MODE 0: relu, split -> Ch/Cl bf16.  MODE 1: fp32 -> Cf.
template<int MODE>
__global__ void __launch_bounds__(256, 2)
k_gemm(const __nv_bfloat16* __restrict__ Ah, const __nv_bfloat16* __restrict__ Al,
       const __nv_bfloat16* __restrict__ Bh, const __nv_bfloat16* __restrict__ Bl,
       const float* __restrict__ bias,
       __nv_bfloat16* __restrict__ Ch, __nv_bfloat16* __restrict__ Cl,
       float* __restrict__ Cf,
       int Mrows, int Ncols, int Kdim)
{
    extern __shared__ uint32_t sm[];
    const uint32_t smb = (uint32_t)__cvta_generic_to_shared(sm);

    const int tid  = threadIdx.x;
    const int wid  = tid >> 5;
    const int lane = tid & 31;
    const int wm   = wid >> 2;
    const int wn   = wid & 3;
    const int m0   = blockIdx.y * 128;
    const int n0   = blockIdx.x * 128;

    float acc[4][4][4];
#pragma unroll
    for (int i = 0; i < 4; ++i)
#pragma unroll
        for (int j = 0; j < 4; ++j)
#pragma unroll
            for (int r = 0; r < 4; ++r) acc[i][j][r] = 0.f;

    const int nc = Kdim >> 5;
    stage_load(smb, 0, Ah, Al, Bh, Bl, m0, n0, 0, Mrows, Kdim, tid);
    cpa_commit();

    for (int c = 0; c < nc; ++c) {
        const int s = c & 1;
        if (c + 1 < nc) {
            stage_load(smb, s ^ 1, Ah, Al, Bh, Bl, m0, n0, (c + 1) << 5, Mrows, Kdim, tid);
            cpa_commit();
            cpa_wait<1>();
        } else {
            cpa_wait<0>();
        }
        __syncthreads();
        const uint32_t* base = sm + s * (STG_B / 4);
        compute_stage(base, base + ARR_B / 4, base + 2 * (ARR_B / 4), base + 3 * (ARR_B / 4),
                      wm, wn, lane, acc);
        __syncthreads();
    }

    // ---- epilogue ----
#pragma unroll
    for (int i = 0; i < 4; ++i) {
#pragma unroll
        for (int j = 0; j < 4; ++j) {
            int cn = n0 + wn * 32 + j * 8 + 2 * (lane & 3);
            float2 bb = *(const float2*)(bias + cn);
            int rm = m0 + wm * 64 + i * 16 + (lane >> 2);
#pragma unroll
            for (int h = 0; h < 2; ++h) {
                int r = rm + h * 8;
                if (r < Mrows) {
                    float vx = acc[i][j][2 * h + 0] + bb.x;
                    float vy = acc[i][j][2 * h + 1] + bb.y;
                    size_t off = (size_t)r * Ncols + cn;
                    if (MODE == 0) {
                        vx = fmaxf(vx, 0.f);
                        vy = fmaxf(vy, 0.f);
                        __nv_bfloat16 hx = __float2bfloat16_rn(vx);
                        __nv_bfloat16 hy = __float2bfloat16_rn(vy);
                        __nv_bfloat16 lx = __float2bfloat16_rn(vx - __bfloat162float(hx));
                        __nv_bfloat16 ly = __float2bfloat16_rn(vy - __bfloat162float(hy));
                        *(uint32_t*)(Ch + off) =
                            ((uint32_t)__bfloat16_as_ushort(hy) << 16) | __bfloat16_as_ushort(hx);
                        *(uint32_t*)(Cl + off) =
                            ((uint32_t)__bfloat16_as_ushort(ly) << 16) | __bfloat16_as_ushort(lx);
                    } else {
                        *(float2*)(Cf + off) = make_float2(vx, vy);
                    }
                }
            }
        }
    }
}

// ---------------- fused propagation ----------------
// out[e] = g0*h[e] + sum_k gamma[k]*P_k[e]*relu(h[idx_k[e]])
__global__ void __launch_bounds__(256)
k_final(const float* __restrict__ gamma, float* __restrict__ out)
{
    int t = blockIdx.x * blockDim.x + threadIdx.x;
    if (t >= EE * (COUT / 4)) return;
    int e = t >> 6;
    int c = (t & 63) << 2;

    float4 hv = *(const float4*)(g_h + (size_t)e * COUT + c);
    float g0 = __ldg(gamma);
    float4 acc;
    acc.x = g0 * hv.x; acc.y = g0 * hv.y;
    acc.z = g0 * hv.z; acc.w = g0 * hv.w;

#pragma unroll
    for (int k = 0; k < KHOPS; ++k) {
        int   idx = g_idx[(size_t)k * EE + e];
        float w   = __ldg(gamma + k + 1) * g_P[(size_t)k * EE + e];
        float4 v  = *(const float4*)(g_h + (size_t)idx * COUT + c);
        acc.x += w * fmaxf(v.x, 0.f);
        acc.y += w * fmaxf(v.y, 0.f);
        acc.z += w * fmaxf(v.z, 0.f);
        acc.w += w * fmaxf(v.w, 0.f);
    }
    *(float4*)(out + (size_t)e * COUT + c) = acc;
}

// ---------------- launch ----------------
extern "C" void kernel_launch(void* const* d_in, const int* in_sizes, int n_in,
                              void* d_out, int out_size)
{
    const float* x     = nullptr;
    const int*   ei    = nullptr;
    const float* W1    = nullptr;
    const float* b1    = nullptr;
    const float* W2    = nullptr;
    const float* b2    = nullptr;
    const float* gamma = nullptr;
    for (int i = 0; i < n_in; ++i) {
        switch (in_sizes[i]) {
            case 102400000: x     = (const float*)d_in[i]; break;
            case 400000:    ei    = (const int*)d_in[i];   break;
            case 262144:    W1    = (const float*)d_in[i]; break;
            case 512:       b1    = (const float*)d_in[i]; break;
            case 131072:    W2    = (const float*)d_in[i]; break;
            case 256:       b2    = (const float*)d_in[i]; break;
            case 11:        gamma = (const float*)d_in[i]; break;
        }
    }
    float* out = (float*)d_out;

    k_detect<<<1, 256>>>(ei);
    k_zero_deg<<<(NN + 255) / 256, 256>>>();
    k_count<<<(EE + 255) / 256, 256>>>(ei);
    k_coef<<<(EE + 255) / 256, 256>>>(ei);

    const int eb = (EE + 255) / 256;
    k_chain_init<<<eb, 256>>>();
    for (int k = 1; k < KHOPS; ++k) k_chain_step<<<eb, 256>>>(k);

    __nv_bfloat16 *w1h, *w1l, *w2h, *w2l, *xh, *xl, *t1h, *t1l;
    float *hbuf;
    cudaGetSymbolAddress((void**)&w1h, g_W1h);
    cudaGetSymbolAddress((void**)&w1l, g_W1l);
    cudaGetSymbolAddress((void**)&w2h, g_W2h);
    cudaGetSymbolAddress((void**)&w2l, g_W2l);
    cudaGetSymbolAddress((void**)&xh,  g_xh);
    cudaGetSymbolAddress((void**)&xl,  g_xl);
    cudaGetSymbolAddress((void**)&t1h, g_t1h);
    cudaGetSymbolAddress((void**)&t1l, g_t1l);
    cudaGetSymbolAddress((void**)&hbuf, g_h);

    k_prep_w<<<(CIN * CHID + 255) / 256, 256>>>(W1, w1h, w1l, CIN, CHID);
    k_prep_w<<<(CHID * COUT + 255) / 256, 256>>>(W2, w2h, w2l, CHID, COUT);

    cudaFuncSetAttribute(k_gemm<0>, cudaFuncAttributeMaxDynamicSharedMemorySize, 2 * STG_B);
    cudaFuncSetAttribute(k_gemm<1>, cudaFuncAttributeMaxDynamicSharedMemorySize, 2 * STG_B);

    const int mt = (CHUNK + 127) / 128;
    dim3 g1(CHID / 128, mt);
    dim3 g2(COUT / 128, mt);
    const int splitN4 = CHUNK * CIN / 4;
    for (int row0 = 0; row0 < NN; row0 += CHUNK) {
        k_split<<<(splitN4 + 255) / 256, 256>>>(x + (size_t)row0 * CIN, xh, xl, splitN4);
        k_gemm<0><<<g1, 256, 2 * STG_B>>>(xh, xl, w1h, w1l, b1,
                                          t1h, t1l, nullptr, CHUNK, CHID, CIN);
        k_gemm<1><<<g2, 256, 2 * STG_B>>>(t1h, t1l, w2h, w2l, b2,
                                          nullptr, nullptr, hbuf + (size_t)row0 * COUT,
                                          CHUNK, COUT, CHID);
    }

    const int total = EE * (COUT / 4);
    k_final<<<(total + 255) / 256, 256>>>(gamma, out);
}